// round 1
// baseline (speedup 1.0000x reference)
#include <cuda_runtime.h>
#include <math.h>

#define NN 50000
#define ER 600000
#define ET 650000   // ER + NN self loops
#define HC 128
#define NB 50

// ---------------- scratch (static device globals; no allocation) -------------
__device__ float    g_x[NN * HC];
__device__ float    g_res[NN * HC];
__device__ float    g_xl[NN * HC];
__device__ float    g_xr[NN * HC];
__device__ float    g_xnew[NN * HC];
__device__ unsigned g_mx[NN * 4];
__device__ float    g_den[NN * 4];
__device__ float    g_elog[ET * 4];      // logits, then exp values in-place
__device__ float    g_mean[NB * HC];
__device__ unsigned g_maxenc[NB * HC];
__device__ float    g_cnt[NB];
__device__ float    g_X[NB * 256];

// ordered-uint encoding of float so atomicMax(unsigned) == float max
__device__ __forceinline__ unsigned encf(float f) {
    unsigned u = __float_as_uint(f);
    return (u & 0x80000000u) ? ~u : (u | 0x80000000u);
}
__device__ __forceinline__ float decf(unsigned u) {
    return __uint_as_float((u & 0x80000000u) ? (u & 0x7fffffffu) : ~u);
}

// ---------------- conv0 linear (K=4) -----------------------------------------
__global__ void gemm0_kernel(const float* __restrict__ nodes,
                             const float* __restrict__ W0l, const float* __restrict__ b0l,
                             const float* __restrict__ W0r, const float* __restrict__ b0r) {
    int i = blockIdx.x * blockDim.x + threadIdx.x;
    if (i >= NN * HC) return;
    int n = i >> 7, c = i & 127;
    float4 nd = *(const float4*)(nodes + n * 4);
    float l = b0l[c] + nd.x * W0l[c] + nd.y * W0l[128 + c] + nd.z * W0l[256 + c] + nd.w * W0l[384 + c];
    float r = b0r[c] + nd.x * W0r[c] + nd.y * W0r[128 + c] + nd.z * W0r[256 + c] + nd.w * W0r[384 + c];
    g_xl[i] = l;
    g_xr[i] = r;
}

// ---------------- dual 128x128 GEMM (xl and xr from one read of x) ------------
// block: 256 threads (16x16); tile: 64 rows x 128 cols; K=128 in chunks of 32
__global__ void gemm_dual_kernel(const float* __restrict__ Wl, const float* __restrict__ bl,
                                 const float* __restrict__ Wr, const float* __restrict__ br) {
    __shared__ float xs[64][33];
    __shared__ float wls[32][128];
    __shared__ float wrs[32][128];
    int tid = threadIdx.x;
    int tx = tid & 15, ty = tid >> 4;
    int row0 = blockIdx.x * 64;
    float accl[4][8], accr[4][8];
#pragma unroll
    for (int i = 0; i < 4; i++)
#pragma unroll
        for (int j = 0; j < 8; j++) { accl[i][j] = 0.f; accr[i][j] = 0.f; }

    for (int kk = 0; kk < HC; kk += 32) {
        // load x tile 64x32
        {
            int r = tid & 63, cseg = tid >> 6;
            int gr = row0 + r;
            float4 v0, v1;
            if (gr < NN) {
                const float4* p = (const float4*)(g_x + gr * HC + kk + cseg * 8);
                v0 = p[0]; v1 = p[1];
            } else {
                v0 = make_float4(0.f, 0.f, 0.f, 0.f);
                v1 = v0;
            }
            int c = cseg * 8;
            xs[r][c + 0] = v0.x; xs[r][c + 1] = v0.y; xs[r][c + 2] = v0.z; xs[r][c + 3] = v0.w;
            xs[r][c + 4] = v1.x; xs[r][c + 5] = v1.y; xs[r][c + 6] = v1.z; xs[r][c + 7] = v1.w;
        }
        // load weight chunks 32x128 each
#pragma unroll
        for (int j = 0; j < 4; j++) {
            int idx = tid + j * 256;          // 0..1023 float4 slots
            int k = idx >> 5;
            int c = (idx & 31) * 4;
            *(float4*)&wls[k][c] = *(const float4*)(Wl + (kk + k) * HC + c);
            *(float4*)&wrs[k][c] = *(const float4*)(Wr + (kk + k) * HC + c);
        }
        __syncthreads();
        int c0 = tx * 8;
#pragma unroll
        for (int k = 0; k < 32; k++) {
            float a[4];
#pragma unroll
            for (int i = 0; i < 4; i++) a[i] = xs[ty * 4 + i][k];
            float wl[8], wr[8];
            *(float4*)&wl[0] = *(float4*)&wls[k][c0];
            *(float4*)&wl[4] = *(float4*)&wls[k][c0 + 4];
            *(float4*)&wr[0] = *(float4*)&wrs[k][c0];
            *(float4*)&wr[4] = *(float4*)&wrs[k][c0 + 4];
#pragma unroll
            for (int i = 0; i < 4; i++)
#pragma unroll
                for (int j = 0; j < 8; j++) {
                    accl[i][j] = fmaf(a[i], wl[j], accl[i][j]);
                    accr[i][j] = fmaf(a[i], wr[j], accr[i][j]);
                }
        }
        __syncthreads();
    }
    int c0 = tx * 8;
    float bbl[8], bbr[8];
#pragma unroll
    for (int j = 0; j < 8; j++) { bbl[j] = bl[c0 + j]; bbr[j] = br[c0 + j]; }
#pragma unroll
    for (int i = 0; i < 4; i++) {
        int gr = row0 + ty * 4 + i;
        if (gr >= NN) continue;
#pragma unroll
        for (int j = 0; j < 8; j++) {
            g_xl[gr * HC + c0 + j] = accl[i][j] + bbl[j];
            g_xr[gr * HC + c0 + j] = accr[i][j] + bbr[j];
        }
    }
}

// ---------------- per-layer zero ---------------------------------------------
__global__ void zero_layer_kernel() {
    int i = blockIdx.x * blockDim.x + threadIdx.x;
    if (i < NN * HC / 4) ((float4*)g_xnew)[i] = make_float4(0.f, 0.f, 0.f, 0.f);
    if (i < NN * 4) { g_mx[i] = 0u; g_den[i] = 0.f; }
}

// ---------------- edge pass 1: logits + segment max --------------------------
// warp per edge; lane handles channels [4*lane, 4*lane+4), head = lane>>3
__global__ void edge_logits_kernel(const int* __restrict__ ei, const float* __restrict__ ea,
                                   const float* __restrict__ We, const float* __restrict__ att) {
    __shared__ float sWe[256];
    __shared__ float sAtt[128];
    int tid = threadIdx.x;
    if (tid < 256) sWe[tid] = We[tid];
    if (tid < 128) sAtt[tid] = att[tid];
    __syncthreads();
    int e = blockIdx.x * 8 + (tid >> 5);
    if (e >= ET) return;
    int lane = tid & 31;
    int s, d;
    if (e < ER) { s = ei[e]; d = ei[ER + e]; }
    else { s = e - ER; d = s; }
    float4 a = *(const float4*)(g_xl + s * HC + lane * 4);
    float4 b = *(const float4*)(g_xr + d * HC + lane * 4);
    float z0 = a.x + b.x, z1 = a.y + b.y, z2 = a.z + b.z, z3 = a.w + b.w;
    if (e < ER) {
        float e0 = ea[2 * e], e1 = ea[2 * e + 1];
        float4 w0 = *(float4*)&sWe[lane * 4];
        float4 w1 = *(float4*)&sWe[128 + lane * 4];
        z0 += e0 * w0.x + e1 * w1.x;
        z1 += e0 * w0.y + e1 * w1.y;
        z2 += e0 * w0.z + e1 * w1.z;
        z3 += e0 * w0.w + e1 * w1.w;
    }
    z0 = z0 > 0.f ? z0 : 0.2f * z0;
    z1 = z1 > 0.f ? z1 : 0.2f * z1;
    z2 = z2 > 0.f ? z2 : 0.2f * z2;
    z3 = z3 > 0.f ? z3 : 0.2f * z3;
    float4 at = *(float4*)&sAtt[lane * 4];
    float p = z0 * at.x + z1 * at.y + z2 * at.z + z3 * at.w;
    p += __shfl_xor_sync(0xffffffffu, p, 1);
    p += __shfl_xor_sync(0xffffffffu, p, 2);
    p += __shfl_xor_sync(0xffffffffu, p, 4);
    if ((lane & 7) == 0) {
        int h = lane >> 3;
        g_elog[e * 4 + h] = p;
        atomicMax(&g_mx[d * 4 + h], encf(p));
    }
}

// ---------------- edge pass 2: exp + denominator -----------------------------
__global__ void edge_softmax_kernel(const int* __restrict__ ei) {
    int i = blockIdx.x * blockDim.x + threadIdx.x;
    if (i >= ET * 4) return;
    int e = i >> 2, h = i & 3;
    int d = (e < ER) ? ei[ER + e] : (e - ER);
    float l = g_elog[i];
    float ex = expf(l - decf(g_mx[d * 4 + h]));
    g_elog[i] = ex;
    atomicAdd(&g_den[d * 4 + h], ex);
}

// ---------------- edge pass 3: weighted aggregation --------------------------
__global__ void edge_aggregate_kernel(const int* __restrict__ ei) {
    int e = blockIdx.x * 8 + (threadIdx.x >> 5);
    if (e >= ET) return;
    int lane = threadIdx.x & 31;
    int s, d;
    if (e < ER) { s = ei[e]; d = ei[ER + e]; }
    else { s = e - ER; d = s; }
    int h = lane >> 3;
    float alpha = g_elog[e * 4 + h] / (g_den[d * 4 + h] + 1e-16f);
    float4 v = *(const float4*)(g_xl + s * HC + lane * 4);
    float* o = g_xnew + d * HC + lane * 4;
    atomicAdd(o + 0, v.x * alpha);
    atomicAdd(o + 1, v.y * alpha);
    atomicAdd(o + 2, v.z * alpha);
    atomicAdd(o + 3, v.w * alpha);
}

// ---------------- finalize: bias + relu + residual ---------------------------
__global__ void finalize_kernel(const float* __restrict__ bias, int add_res, int write_res) {
    int i = blockIdx.x * blockDim.x + threadIdx.x;
    if (i >= NN * HC) return;
    float v = g_xnew[i] + bias[i & 127];
    v = fmaxf(v, 0.f);
    if (add_res) v += g_res[i];
    g_x[i] = v;
    if (write_res) g_res[i] = v;
}

// ---------------- pooling -----------------------------------------------------
__global__ void zero_pool_kernel() {
    int i = blockIdx.x * blockDim.x + threadIdx.x;
    if (i < NB * HC) { g_mean[i] = 0.f; g_maxenc[i] = 0u; }
    if (i < NB) g_cnt[i] = 0.f;
}

__global__ void pool_acc_kernel(const int* __restrict__ batch) {
    int i = blockIdx.x * blockDim.x + threadIdx.x;
    if (i >= NN * 32) return;
    int n = i >> 5, q = i & 31;
    int b = batch[n];
    float4 v = *(const float4*)(g_x + n * HC + q * 4);
    int base = b * HC + q * 4;
    atomicAdd(&g_mean[base + 0], v.x);
    atomicAdd(&g_mean[base + 1], v.y);
    atomicAdd(&g_mean[base + 2], v.z);
    atomicAdd(&g_mean[base + 3], v.w);
    atomicMax(&g_maxenc[base + 0], encf(v.x));
    atomicMax(&g_maxenc[base + 1], encf(v.y));
    atomicMax(&g_maxenc[base + 2], encf(v.z));
    atomicMax(&g_maxenc[base + 3], encf(v.w));
    if (q == 0) atomicAdd(&g_cnt[b], 1.f);
}

__global__ void pool_fin_kernel() {
    int i = blockIdx.x * blockDim.x + threadIdx.x;
    if (i >= NB * HC) return;
    int b = i >> 7, c = i & 127;
    float cnt = g_cnt[b];
    g_X[b * 256 + c] = g_mean[i] / fmaxf(cnt, 1.f);
    g_X[b * 256 + 128 + c] = (cnt > 0.f) ? decf(g_maxenc[i]) : 0.f;
}

// ---------------- dense trunk + heads (one block per graph) -------------------
__global__ void dense_kernel(const float* __restrict__ D1W, const float* __restrict__ D1b,
                             const float* __restrict__ D23W, const float* __restrict__ D23b,
                             const float* __restrict__ H1W, const float* __restrict__ H1b,
                             const float* __restrict__ H2W, const float* __restrict__ H2b,
                             const float* __restrict__ H3W, const float* __restrict__ H3b,
                             float* __restrict__ out) {
    __shared__ float sA[256];
    __shared__ float sB[128];
    __shared__ float sX3[128];
    int b = blockIdx.x, t = threadIdx.x;
    sA[t] = g_X[b * 256 + t];
    sA[t + 128] = g_X[b * 256 + 128 + t];
    __syncthreads();
    // D1: 256 -> 128
    float acc = D1b[t];
    for (int k = 0; k < 256; k++) acc = fmaf(sA[k], D1W[k * 128 + t], acc);
    acc = fmaxf(acc, 0.f);
    sB[t] = acc;
    __syncthreads();
    // D2: 128 -> 128
    acc = D23b[t];
    for (int k = 0; k < 128; k++) acc = fmaf(sB[k], D23W[k * 128 + t], acc);
    acc = fmaxf(acc, 0.f);
    __syncthreads();
    sA[t] = acc;
    __syncthreads();
    // D3: 128 -> 128
    acc = D23b[128 + t];
    for (int k = 0; k < 128; k++) acc = fmaf(sA[k], D23W[16384 + k * 128 + t], acc);
    sX3[t] = fmaxf(acc, 0.f);
    __syncthreads();
    // heads
    for (int h = 0; h < 3; h++) {
        float a1 = H1b[h * 128 + t];
        for (int k = 0; k < 128; k++) a1 = fmaf(sX3[k], H1W[h * 16384 + k * 128 + t], a1);
        a1 = fmaxf(a1, 0.f);
        sB[t] = a1;
        __syncthreads();
        float a2 = 0.f;
        if (t < 64) {
            a2 = H2b[h * 64 + t];
            for (int k = 0; k < 128; k++) a2 = fmaf(sB[k], H2W[h * 8192 + k * 64 + t], a2);
            a2 = fmaxf(a2, 0.f);
        }
        __syncthreads();
        if (t < 64) sA[t] = a2;
        __syncthreads();
        if (t == 0) {
            float y = H3b[h];
            for (int k = 0; k < 64; k++) y = fmaf(sA[k], H3W[h * 64 + k], y);
            if (h == 0) y = tanhf(y);
            out[b * 3 + h] = y;
        }
        __syncthreads();
    }
}

// ---------------- host ---------------------------------------------------------
static void run_edges(const int* ei, const float* ea, const float* We, const float* att,
                      const float* bias, int add_res, int write_res) {
    zero_layer_kernel<<<(NN * HC / 4 + 255) / 256, 256>>>();
    edge_logits_kernel<<<(ET + 7) / 8, 256>>>(ei, ea, We, att);
    edge_softmax_kernel<<<(ET * 4 + 255) / 256, 256>>>(ei);
    edge_aggregate_kernel<<<(ET + 7) / 8, 256>>>(ei);
    finalize_kernel<<<(NN * HC + 255) / 256, 256>>>(bias, add_res, write_res);
}

extern "C" void kernel_launch(void* const* d_in, const int* in_sizes, int n_in,
                              void* d_out, int out_size) {
    const float* nodes = (const float*)d_in[0];
    const int*   ei    = (const int*)d_in[1];
    const float* ea    = (const float*)d_in[2];
    const int*   batch = (const int*)d_in[3];
    const float* W0l = (const float*)d_in[4];
    const float* b0l = (const float*)d_in[5];
    const float* W0r = (const float*)d_in[6];
    const float* b0r = (const float*)d_in[7];
    const float* W0e = (const float*)d_in[8];
    const float* att0 = (const float*)d_in[9];
    const float* bias0 = (const float*)d_in[10];
    const float* Wl = (const float*)d_in[11];
    const float* bl = (const float*)d_in[12];
    const float* Wr = (const float*)d_in[13];
    const float* br = (const float*)d_in[14];
    const float* We = (const float*)d_in[15];
    const float* atts = (const float*)d_in[16];
    const float* biases = (const float*)d_in[17];
    const float* D1W = (const float*)d_in[18];
    const float* D1b = (const float*)d_in[19];
    const float* D23W = (const float*)d_in[20];
    const float* D23b = (const float*)d_in[21];
    const float* H1W = (const float*)d_in[22];
    const float* H1b = (const float*)d_in[23];
    const float* H2W = (const float*)d_in[24];
    const float* H2b = (const float*)d_in[25];
    const float* H3W = (const float*)d_in[26];
    const float* H3b = (const float*)d_in[27];
    float* out = (float*)d_out;

    // conv0 (input dim 4)
    gemm0_kernel<<<(NN * HC + 255) / 256, 256>>>(nodes, W0l, b0l, W0r, b0r);
    run_edges(ei, ea, W0e, att0, bias0, /*add_res=*/0, /*write_res=*/1);

    // 8 stacked convs (4 skip blocks x 2)
    for (int t = 0; t < 8; t++) {
        gemm_dual_kernel<<<(NN + 63) / 64, 256>>>(Wl + t * 16384, bl + t * 128,
                                                  Wr + t * 16384, br + t * 128);
        int second = (t & 1);
        run_edges(ei, ea, We + t * 256, atts + t * 128, biases + t * 128,
                  /*add_res=*/second, /*write_res=*/second);
    }

    // pooling
    zero_pool_kernel<<<(NB * HC + 255) / 256, 256>>>();
    pool_acc_kernel<<<(NN * 32 + 255) / 256, 256>>>(batch);
    pool_fin_kernel<<<(NB * HC + 127) / 128, 128>>>();

    // dense trunk + 3 heads
    dense_kernel<<<NB, 128>>>(D1W, D1b, D23W, D23b, H1W, H1b, H2W, H2b, H3W, H3b, out);
}

// round 2
// speedup vs baseline: 1.7838x; 1.7838x over previous
#include <cuda_runtime.h>
#include <math.h>

#define NN 50000
#define ER 600000
#define HC 128
#define NB 50

// ---------------- scratch (static device globals; no allocation) -------------
__device__ float    g_x[NN * HC];
__device__ float    g_res[NN * HC];
__device__ float    g_xl[NN * HC];
__device__ float    g_xr[NN * HC];
__device__ int      g_deg[NN];
__device__ int      g_rowptr[NN + 1];
__device__ int      g_cur[NN];
__device__ int      g_csrc[ER];
__device__ float2   g_cea[ER];
__device__ float    g_mean[NB * HC];
__device__ unsigned g_maxenc[NB * HC];
__device__ float    g_cnt[NB];
__device__ float    g_X[NB * 256];

// ordered-uint encoding of float so atomicMax(unsigned) == float max
__device__ __forceinline__ unsigned encf(float f) {
    unsigned u = __float_as_uint(f);
    return (u & 0x80000000u) ? ~u : (u | 0x80000000u);
}
__device__ __forceinline__ float decf(unsigned u) {
    return __uint_as_float((u & 0x80000000u) ? (u & 0x7fffffffu) : ~u);
}

// ---------------- CSR build (once per call) -----------------------------------
__global__ void csr_zero_kernel() {
    int i = blockIdx.x * blockDim.x + threadIdx.x;
    if (i < NN) g_deg[i] = 0;
}
__global__ void csr_hist_kernel(const int* __restrict__ ei) {
    int e = blockIdx.x * blockDim.x + threadIdx.x;
    if (e < ER) atomicAdd(&g_deg[ei[ER + e]], 1);
}
// single block, 1024 threads: exclusive scan of g_deg -> g_rowptr, g_cur
__global__ void csr_scan_kernel() {
    __shared__ int ps[1024];
    int t = threadIdx.x;
    const int CH = (NN + 1023) / 1024;  // 49
    int base = t * CH;
    int sum = 0;
    for (int j = 0; j < CH; j++) {
        int i = base + j;
        if (i < NN) sum += g_deg[i];
    }
    ps[t] = sum;
    __syncthreads();
    for (int off = 1; off < 1024; off <<= 1) {
        int v = (t >= off) ? ps[t - off] : 0;
        __syncthreads();
        ps[t] += v;
        __syncthreads();
    }
    int run = (t == 0) ? 0 : ps[t - 1];
    for (int j = 0; j < CH; j++) {
        int i = base + j;
        if (i < NN) {
            g_rowptr[i] = run;
            g_cur[i] = run;
            run += g_deg[i];
        }
    }
    if (t == 1023) g_rowptr[NN] = ps[1023];
}
__global__ void csr_scatter_kernel(const int* __restrict__ ei, const float* __restrict__ ea) {
    int e = blockIdx.x * blockDim.x + threadIdx.x;
    if (e >= ER) return;
    int s = ei[e], d = ei[ER + e];
    int p = atomicAdd(&g_cur[d], 1);
    g_csrc[p] = s;
    g_cea[p] = make_float2(ea[2 * e], ea[2 * e + 1]);
}

// ---------------- conv0 linear (K=4) -----------------------------------------
__global__ void gemm0_kernel(const float* __restrict__ nodes,
                             const float* __restrict__ W0l, const float* __restrict__ b0l,
                             const float* __restrict__ W0r, const float* __restrict__ b0r) {
    int i = blockIdx.x * blockDim.x + threadIdx.x;
    if (i >= NN * HC) return;
    int n = i >> 7, c = i & 127;
    float4 nd = *(const float4*)(nodes + n * 4);
    float l = b0l[c] + nd.x * W0l[c] + nd.y * W0l[128 + c] + nd.z * W0l[256 + c] + nd.w * W0l[384 + c];
    float r = b0r[c] + nd.x * W0r[c] + nd.y * W0r[128 + c] + nd.z * W0r[256 + c] + nd.w * W0r[384 + c];
    g_xl[i] = l;
    g_xr[i] = r;
}

// ---------------- dual 128x128 GEMM (xl and xr from one read of x) ------------
__global__ void __launch_bounds__(256) gemm_dual_kernel(
        const float* __restrict__ Wl, const float* __restrict__ bl,
        const float* __restrict__ Wr, const float* __restrict__ br) {
    __shared__ float xs[64][33];
    __shared__ float wls[32][128];
    __shared__ float wrs[32][128];
    int tid = threadIdx.x;
    int tx = tid & 15, ty = tid >> 4;
    int row0 = blockIdx.x * 64;
    float accl[4][8], accr[4][8];
#pragma unroll
    for (int i = 0; i < 4; i++)
#pragma unroll
        for (int j = 0; j < 8; j++) { accl[i][j] = 0.f; accr[i][j] = 0.f; }

    for (int kk = 0; kk < HC; kk += 32) {
        {
            int r = tid & 63, cseg = tid >> 6;
            int gr = row0 + r;
            float4 v0, v1;
            if (gr < NN) {
                const float4* p = (const float4*)(g_x + gr * HC + kk + cseg * 8);
                v0 = p[0]; v1 = p[1];
            } else {
                v0 = make_float4(0.f, 0.f, 0.f, 0.f);
                v1 = v0;
            }
            int c = cseg * 8;
            xs[r][c + 0] = v0.x; xs[r][c + 1] = v0.y; xs[r][c + 2] = v0.z; xs[r][c + 3] = v0.w;
            xs[r][c + 4] = v1.x; xs[r][c + 5] = v1.y; xs[r][c + 6] = v1.z; xs[r][c + 7] = v1.w;
        }
#pragma unroll
        for (int j = 0; j < 4; j++) {
            int idx = tid + j * 256;
            int k = idx >> 5;
            int c = (idx & 31) * 4;
            *(float4*)&wls[k][c] = *(const float4*)(Wl + (kk + k) * HC + c);
            *(float4*)&wrs[k][c] = *(const float4*)(Wr + (kk + k) * HC + c);
        }
        __syncthreads();
        int c0 = tx * 8;
#pragma unroll
        for (int k = 0; k < 32; k++) {
            float a[4];
#pragma unroll
            for (int i = 0; i < 4; i++) a[i] = xs[ty * 4 + i][k];
            float wl[8], wr[8];
            *(float4*)&wl[0] = *(float4*)&wls[k][c0];
            *(float4*)&wl[4] = *(float4*)&wls[k][c0 + 4];
            *(float4*)&wr[0] = *(float4*)&wrs[k][c0];
            *(float4*)&wr[4] = *(float4*)&wrs[k][c0 + 4];
#pragma unroll
            for (int i = 0; i < 4; i++)
#pragma unroll
                for (int j = 0; j < 8; j++) {
                    accl[i][j] = fmaf(a[i], wl[j], accl[i][j]);
                    accr[i][j] = fmaf(a[i], wr[j], accr[i][j]);
                }
        }
        __syncthreads();
    }
    int c0 = tx * 8;
    float bbl[8], bbr[8];
#pragma unroll
    for (int j = 0; j < 8; j++) { bbl[j] = bl[c0 + j]; bbr[j] = br[c0 + j]; }
#pragma unroll
    for (int i = 0; i < 4; i++) {
        int gr = row0 + ty * 4 + i;
        if (gr >= NN) continue;
#pragma unroll
        for (int j = 0; j < 8; j++) {
            g_xl[gr * HC + c0 + j] = accl[i][j] + bbl[j];
            g_xr[gr * HC + c0 + j] = accr[i][j] + bbr[j];
        }
    }
}

// ---------------- fused GATv2 layer: warp per dst node, online softmax --------
// lane c0 = lane*4 channels, head h = lane>>3 (8 lanes per head)
__global__ void __launch_bounds__(256) gat_layer_kernel(
        const float* __restrict__ We, const float* __restrict__ att,
        const float* __restrict__ bias, int add_res, int write_res) {
    __shared__ float sWe[256];
    __shared__ float sAtt[128];
    int tid = threadIdx.x;
    if (tid < 256) sWe[tid] = We[tid];
    if (tid < 128) sAtt[tid] = att[tid];
    __syncthreads();

    int n = blockIdx.x * 8 + (tid >> 5);
    if (n >= NN) return;
    int lane = tid & 31, c0 = lane * 4;

    float4 w0 = *(float4*)&sWe[c0];
    float4 w1 = *(float4*)&sWe[128 + c0];
    float4 at = *(float4*)&sAtt[c0];
    float4 xr = *(const float4*)(g_xr + n * HC + c0);
    float4 xls = *(const float4*)(g_xl + n * HC + c0);

    // self-loop logit (ea = 0)
    float z0 = xls.x + xr.x, z1 = xls.y + xr.y, z2 = xls.z + xr.z, z3 = xls.w + xr.w;
    z0 = z0 > 0.f ? z0 : 0.2f * z0;
    z1 = z1 > 0.f ? z1 : 0.2f * z1;
    z2 = z2 > 0.f ? z2 : 0.2f * z2;
    z3 = z3 > 0.f ? z3 : 0.2f * z3;
    float pself = z0 * at.x + z1 * at.y + z2 * at.z + z3 * at.w;
    pself += __shfl_xor_sync(0xffffffffu, pself, 1);
    pself += __shfl_xor_sync(0xffffffffu, pself, 2);
    pself += __shfl_xor_sync(0xffffffffu, pself, 4);

    int beg = g_rowptr[n], end = g_rowptr[n + 1];

    // pass A: online max / sum
    float m = pself, s = 1.0f;
    for (int p = beg; p < end; p++) {
        int src = g_csrc[p];
        float2 eav = g_cea[p];
        float4 xl = *(const float4*)(g_xl + src * HC + c0);
        float y0 = fmaf(eav.x, w0.x, fmaf(eav.y, w1.x, xl.x + xr.x));
        float y1 = fmaf(eav.x, w0.y, fmaf(eav.y, w1.y, xl.y + xr.y));
        float y2 = fmaf(eav.x, w0.z, fmaf(eav.y, w1.z, xl.z + xr.z));
        float y3 = fmaf(eav.x, w0.w, fmaf(eav.y, w1.w, xl.w + xr.w));
        y0 = y0 > 0.f ? y0 : 0.2f * y0;
        y1 = y1 > 0.f ? y1 : 0.2f * y1;
        y2 = y2 > 0.f ? y2 : 0.2f * y2;
        y3 = y3 > 0.f ? y3 : 0.2f * y3;
        float q = y0 * at.x + y1 * at.y + y2 * at.z + y3 * at.w;
        q += __shfl_xor_sync(0xffffffffu, q, 1);
        q += __shfl_xor_sync(0xffffffffu, q, 2);
        q += __shfl_xor_sync(0xffffffffu, q, 4);
        float mn = fmaxf(m, q);
        s = s * __expf(m - mn) + __expf(q - mn);
        m = mn;
    }
    float inv = 1.0f / (s + 1e-16f);

    // pass B: alpha-weighted aggregation (recompute logits bit-identically)
    float asel = __expf(pself - m) * inv;
    float4 acc;
    acc.x = xls.x * asel; acc.y = xls.y * asel; acc.z = xls.z * asel; acc.w = xls.w * asel;
    for (int p = beg; p < end; p++) {
        int src = g_csrc[p];
        float2 eav = g_cea[p];
        float4 xl = *(const float4*)(g_xl + src * HC + c0);
        float y0 = fmaf(eav.x, w0.x, fmaf(eav.y, w1.x, xl.x + xr.x));
        float y1 = fmaf(eav.x, w0.y, fmaf(eav.y, w1.y, xl.y + xr.y));
        float y2 = fmaf(eav.x, w0.z, fmaf(eav.y, w1.z, xl.z + xr.z));
        float y3 = fmaf(eav.x, w0.w, fmaf(eav.y, w1.w, xl.w + xr.w));
        y0 = y0 > 0.f ? y0 : 0.2f * y0;
        y1 = y1 > 0.f ? y1 : 0.2f * y1;
        y2 = y2 > 0.f ? y2 : 0.2f * y2;
        y3 = y3 > 0.f ? y3 : 0.2f * y3;
        float q = y0 * at.x + y1 * at.y + y2 * at.z + y3 * at.w;
        q += __shfl_xor_sync(0xffffffffu, q, 1);
        q += __shfl_xor_sync(0xffffffffu, q, 2);
        q += __shfl_xor_sync(0xffffffffu, q, 4);
        float al = __expf(q - m) * inv;
        acc.x = fmaf(xl.x, al, acc.x);
        acc.y = fmaf(xl.y, al, acc.y);
        acc.z = fmaf(xl.z, al, acc.z);
        acc.w = fmaf(xl.w, al, acc.w);
    }

    float4 bv = *(const float4*)(bias + c0);
    float4 o;
    o.x = fmaxf(acc.x + bv.x, 0.f);
    o.y = fmaxf(acc.y + bv.y, 0.f);
    o.z = fmaxf(acc.z + bv.z, 0.f);
    o.w = fmaxf(acc.w + bv.w, 0.f);
    if (add_res) {
        float4 r = *(const float4*)(g_res + n * HC + c0);
        o.x += r.x; o.y += r.y; o.z += r.z; o.w += r.w;
    }
    *(float4*)(g_x + n * HC + c0) = o;
    if (write_res) *(float4*)(g_res + n * HC + c0) = o;
}

// ---------------- pooling (exploit sorted batch: local acc, flush on change) ---
__global__ void zero_pool_kernel() {
    int i = blockIdx.x * blockDim.x + threadIdx.x;
    if (i < NB * HC) { g_mean[i] = 0.f; g_maxenc[i] = 0u; }
    if (i < NB) g_cnt[i] = 0.f;
}

#define POOL_CH 200
__global__ void pool_acc_kernel(const int* __restrict__ batch) {
    int c = threadIdx.x;  // 0..127 channel
    int n0 = blockIdx.x * POOL_CH;
    int n1 = n0 + POOL_CH;
    if (n1 > NN) n1 = NN;
    if (n0 >= NN) return;
    int curb = batch[n0];
    float sm = 0.f, mxv = -INFINITY, cnt = 0.f;
    for (int n = n0; n < n1; n++) {
        int b = batch[n];
        if (b != curb) {
            atomicAdd(&g_mean[curb * HC + c], sm);
            atomicMax(&g_maxenc[curb * HC + c], encf(mxv));
            if (c == 0) atomicAdd(&g_cnt[curb], cnt);
            sm = 0.f; mxv = -INFINITY; cnt = 0.f; curb = b;
        }
        float v = g_x[n * HC + c];
        sm += v;
        mxv = fmaxf(mxv, v);
        cnt += 1.f;
    }
    atomicAdd(&g_mean[curb * HC + c], sm);
    atomicMax(&g_maxenc[curb * HC + c], encf(mxv));
    if (c == 0) atomicAdd(&g_cnt[curb], cnt);
}

__global__ void pool_fin_kernel() {
    int i = blockIdx.x * blockDim.x + threadIdx.x;
    if (i >= NB * HC) return;
    int b = i >> 7, c = i & 127;
    float cnt = g_cnt[b];
    g_X[b * 256 + c] = g_mean[i] / fmaxf(cnt, 1.f);
    g_X[b * 256 + 128 + c] = (cnt > 0.f) ? decf(g_maxenc[i]) : 0.f;
}

// ---------------- dense trunk + heads (one block per graph) -------------------
__global__ void dense_kernel(const float* __restrict__ D1W, const float* __restrict__ D1b,
                             const float* __restrict__ D23W, const float* __restrict__ D23b,
                             const float* __restrict__ H1W, const float* __restrict__ H1b,
                             const float* __restrict__ H2W, const float* __restrict__ H2b,
                             const float* __restrict__ H3W, const float* __restrict__ H3b,
                             float* __restrict__ out) {
    __shared__ float sA[256];
    __shared__ float sB[128];
    __shared__ float sX3[128];
    int b = blockIdx.x, t = threadIdx.x;
    sA[t] = g_X[b * 256 + t];
    sA[t + 128] = g_X[b * 256 + 128 + t];
    __syncthreads();
    float acc = D1b[t];
    for (int k = 0; k < 256; k++) acc = fmaf(sA[k], D1W[k * 128 + t], acc);
    acc = fmaxf(acc, 0.f);
    sB[t] = acc;
    __syncthreads();
    acc = D23b[t];
    for (int k = 0; k < 128; k++) acc = fmaf(sB[k], D23W[k * 128 + t], acc);
    acc = fmaxf(acc, 0.f);
    __syncthreads();
    sA[t] = acc;
    __syncthreads();
    acc = D23b[128 + t];
    for (int k = 0; k < 128; k++) acc = fmaf(sA[k], D23W[16384 + k * 128 + t], acc);
    sX3[t] = fmaxf(acc, 0.f);
    __syncthreads();
    for (int h = 0; h < 3; h++) {
        float a1 = H1b[h * 128 + t];
        for (int k = 0; k < 128; k++) a1 = fmaf(sX3[k], H1W[h * 16384 + k * 128 + t], a1);
        a1 = fmaxf(a1, 0.f);
        sB[t] = a1;
        __syncthreads();
        float a2 = 0.f;
        if (t < 64) {
            a2 = H2b[h * 64 + t];
            for (int k = 0; k < 128; k++) a2 = fmaf(sB[k], H2W[h * 8192 + k * 64 + t], a2);
            a2 = fmaxf(a2, 0.f);
        }
        __syncthreads();
        if (t < 64) sA[t] = a2;
        __syncthreads();
        if (t == 0) {
            float y = H3b[h];
            for (int k = 0; k < 64; k++) y = fmaf(sA[k], H3W[h * 64 + k], y);
            if (h == 0) y = tanhf(y);
            out[b * 3 + h] = y;
        }
        __syncthreads();
    }
}

// ---------------- host ---------------------------------------------------------
extern "C" void kernel_launch(void* const* d_in, const int* in_sizes, int n_in,
                              void* d_out, int out_size) {
    const float* nodes = (const float*)d_in[0];
    const int*   ei    = (const int*)d_in[1];
    const float* ea    = (const float*)d_in[2];
    const int*   batch = (const int*)d_in[3];
    const float* W0l = (const float*)d_in[4];
    const float* b0l = (const float*)d_in[5];
    const float* W0r = (const float*)d_in[6];
    const float* b0r = (const float*)d_in[7];
    const float* W0e = (const float*)d_in[8];
    const float* att0 = (const float*)d_in[9];
    const float* bias0 = (const float*)d_in[10];
    const float* Wl = (const float*)d_in[11];
    const float* bl = (const float*)d_in[12];
    const float* Wr = (const float*)d_in[13];
    const float* br = (const float*)d_in[14];
    const float* We = (const float*)d_in[15];
    const float* atts = (const float*)d_in[16];
    const float* biases = (const float*)d_in[17];
    const float* D1W = (const float*)d_in[18];
    const float* D1b = (const float*)d_in[19];
    const float* D23W = (const float*)d_in[20];
    const float* D23b = (const float*)d_in[21];
    const float* H1W = (const float*)d_in[22];
    const float* H1b = (const float*)d_in[23];
    const float* H2W = (const float*)d_in[24];
    const float* H2b = (const float*)d_in[25];
    const float* H3W = (const float*)d_in[26];
    const float* H3b = (const float*)d_in[27];
    float* out = (float*)d_out;

    // CSR build (reused for all 9 layers)
    csr_zero_kernel<<<(NN + 255) / 256, 256>>>();
    csr_hist_kernel<<<(ER + 255) / 256, 256>>>(ei);
    csr_scan_kernel<<<1, 1024>>>();
    csr_scatter_kernel<<<(ER + 255) / 256, 256>>>(ei, ea);

    // conv0 (input dim 4)
    gemm0_kernel<<<(NN * HC + 255) / 256, 256>>>(nodes, W0l, b0l, W0r, b0r);
    gat_layer_kernel<<<(NN + 7) / 8, 256>>>(W0e, att0, bias0, 0, 1);

    // 8 stacked convs (4 skip blocks x 2)
    for (int t = 0; t < 8; t++) {
        gemm_dual_kernel<<<(NN + 63) / 64, 256>>>(Wl + t * 16384, bl + t * 128,
                                                  Wr + t * 16384, br + t * 128);
        int second = (t & 1);
        gat_layer_kernel<<<(NN + 7) / 8, 256>>>(We + t * 256, atts + t * 128,
                                                biases + t * 128, second, second);
    }

    // pooling
    zero_pool_kernel<<<(NB * HC + 255) / 256, 256>>>();
    pool_acc_kernel<<<(NN + POOL_CH - 1) / POOL_CH, 128>>>(batch);
    pool_fin_kernel<<<(NB * HC + 127) / 128, 128>>>();

    // dense trunk + 3 heads
    dense_kernel<<<NB, 128>>>(D1W, D1b, D23W, D23b, H1W, H1b, H2W, H2b, H3W, H3b, out);
}

// round 3
// speedup vs baseline: 2.0404x; 1.1438x over previous
#include <cuda_runtime.h>
#include <math.h>

#define NN 50000
#define ER 600000
#define HC 128
#define NB 50

// ---------------- scratch (static device globals; no allocation) -------------
__device__ float    g_x[NN * HC];
__device__ float    g_res[NN * HC];
__device__ float    g_xl[NN * HC];
__device__ float    g_xr[NN * HC];
__device__ int      g_deg[NN];
__device__ int      g_rowptr[NN + 1];
__device__ int      g_cur[NN];
__device__ int      g_csrc[ER];
__device__ float2   g_cea[ER];
__device__ float    g_mean[NB * HC];
__device__ unsigned g_maxenc[NB * HC];
__device__ float    g_cnt[NB];
__device__ float    g_X[NB * 256];

// ordered-uint encoding of float so atomicMax(unsigned) == float max
__device__ __forceinline__ unsigned encf(float f) {
    unsigned u = __float_as_uint(f);
    return (u & 0x80000000u) ? ~u : (u | 0x80000000u);
}
__device__ __forceinline__ float decf(unsigned u) {
    return __uint_as_float((u & 0x80000000u) ? (u & 0x7fffffffu) : ~u);
}

// ---------------- CSR build (once per call) -----------------------------------
__global__ void csr_zero_kernel() {
    int i = blockIdx.x * blockDim.x + threadIdx.x;
    if (i < NN) g_deg[i] = 0;
}
__global__ void csr_hist_kernel(const int* __restrict__ ei) {
    int e = blockIdx.x * blockDim.x + threadIdx.x;
    if (e < ER) atomicAdd(&g_deg[ei[ER + e]], 1);
}
__global__ void csr_scan_kernel() {
    __shared__ int ps[1024];
    int t = threadIdx.x;
    const int CH = (NN + 1023) / 1024;  // 49
    int base = t * CH;
    int sum = 0;
    for (int j = 0; j < CH; j++) {
        int i = base + j;
        if (i < NN) sum += g_deg[i];
    }
    ps[t] = sum;
    __syncthreads();
    for (int off = 1; off < 1024; off <<= 1) {
        int v = (t >= off) ? ps[t - off] : 0;
        __syncthreads();
        ps[t] += v;
        __syncthreads();
    }
    int run = (t == 0) ? 0 : ps[t - 1];
    for (int j = 0; j < CH; j++) {
        int i = base + j;
        if (i < NN) {
            g_rowptr[i] = run;
            g_cur[i] = run;
            run += g_deg[i];
        }
    }
    if (t == 1023) g_rowptr[NN] = ps[1023];
}
__global__ void csr_scatter_kernel(const int* __restrict__ ei, const float* __restrict__ ea) {
    int e = blockIdx.x * blockDim.x + threadIdx.x;
    if (e >= ER) return;
    int s = ei[e], d = ei[ER + e];
    int p = atomicAdd(&g_cur[d], 1);
    g_csrc[p] = s;
    g_cea[p] = make_float2(ea[2 * e], ea[2 * e + 1]);
}

// ---------------- conv0 linear (K=4) -----------------------------------------
__global__ void gemm0_kernel(const float* __restrict__ nodes,
                             const float* __restrict__ W0l, const float* __restrict__ b0l,
                             const float* __restrict__ W0r, const float* __restrict__ b0r) {
    int i = blockIdx.x * blockDim.x + threadIdx.x;
    if (i >= NN * HC) return;
    int n = i >> 7, c = i & 127;
    float4 nd = *(const float4*)(nodes + n * 4);
    float l = b0l[c] + nd.x * W0l[c] + nd.y * W0l[128 + c] + nd.z * W0l[256 + c] + nd.w * W0l[384 + c];
    float r = b0r[c] + nd.x * W0r[c] + nd.y * W0r[128 + c] + nd.z * W0r[256 + c] + nd.w * W0r[384 + c];
    g_xl[i] = l;
    g_xr[i] = r;
}

// ---------------- dual 128x128 GEMM (xl and xr from one read of x) ------------
__global__ void __launch_bounds__(256) gemm_dual_kernel(
        const float* __restrict__ Wl, const float* __restrict__ bl,
        const float* __restrict__ Wr, const float* __restrict__ br) {
    __shared__ float xs[64][33];
    __shared__ float wls[32][128];
    __shared__ float wrs[32][128];
    int tid = threadIdx.x;
    int tx = tid & 15, ty = tid >> 4;
    int row0 = blockIdx.x * 64;
    float accl[4][8], accr[4][8];
#pragma unroll
    for (int i = 0; i < 4; i++)
#pragma unroll
        for (int j = 0; j < 8; j++) { accl[i][j] = 0.f; accr[i][j] = 0.f; }

    for (int kk = 0; kk < HC; kk += 32) {
        {
            int r = tid & 63, cseg = tid >> 6;
            int gr = row0 + r;
            float4 v0, v1;
            if (gr < NN) {
                const float4* p = (const float4*)(g_x + gr * HC + kk + cseg * 8);
                v0 = p[0]; v1 = p[1];
            } else {
                v0 = make_float4(0.f, 0.f, 0.f, 0.f);
                v1 = v0;
            }
            int c = cseg * 8;
            xs[r][c + 0] = v0.x; xs[r][c + 1] = v0.y; xs[r][c + 2] = v0.z; xs[r][c + 3] = v0.w;
            xs[r][c + 4] = v1.x; xs[r][c + 5] = v1.y; xs[r][c + 6] = v1.z; xs[r][c + 7] = v1.w;
        }
#pragma unroll
        for (int j = 0; j < 4; j++) {
            int idx = tid + j * 256;
            int k = idx >> 5;
            int c = (idx & 31) * 4;
            *(float4*)&wls[k][c] = *(const float4*)(Wl + (kk + k) * HC + c);
            *(float4*)&wrs[k][c] = *(const float4*)(Wr + (kk + k) * HC + c);
        }
        __syncthreads();
        int c0 = tx * 8;
#pragma unroll
        for (int k = 0; k < 32; k++) {
            float a[4];
#pragma unroll
            for (int i = 0; i < 4; i++) a[i] = xs[ty * 4 + i][k];
            float wl[8], wr[8];
            *(float4*)&wl[0] = *(float4*)&wls[k][c0];
            *(float4*)&wl[4] = *(float4*)&wls[k][c0 + 4];
            *(float4*)&wr[0] = *(float4*)&wrs[k][c0];
            *(float4*)&wr[4] = *(float4*)&wrs[k][c0 + 4];
#pragma unroll
            for (int i = 0; i < 4; i++)
#pragma unroll
                for (int j = 0; j < 8; j++) {
                    accl[i][j] = fmaf(a[i], wl[j], accl[i][j]);
                    accr[i][j] = fmaf(a[i], wr[j], accr[i][j]);
                }
        }
        __syncthreads();
    }
    int c0 = tx * 8;
    float bbl[8], bbr[8];
#pragma unroll
    for (int j = 0; j < 8; j++) { bbl[j] = bl[c0 + j]; bbr[j] = br[c0 + j]; }
#pragma unroll
    for (int i = 0; i < 4; i++) {
        int gr = row0 + ty * 4 + i;
        if (gr >= NN) continue;
#pragma unroll
        for (int j = 0; j < 8; j++) {
            g_xl[gr * HC + c0 + j] = accl[i][j] + bbl[j];
            g_xr[gr * HC + c0 + j] = accr[i][j] + bbr[j];
        }
    }
}

// ---------------- fused GATv2 layer: warp per dst node, SINGLE-PASS softmax ---
// lane c0 = lane*4 channels, head h = lane>>3 (8 lanes per head)
__global__ void __launch_bounds__(256) gat_layer_kernel(
        const float* __restrict__ We, const float* __restrict__ att,
        const float* __restrict__ bias, int add_res, int write_res) {
    __shared__ float sWe[256];
    __shared__ float sAtt[128];
    int tid = threadIdx.x;
    if (tid < 256) sWe[tid] = We[tid];
    if (tid < 128) sAtt[tid] = att[tid];
    __syncthreads();

    int n = blockIdx.x * 8 + (tid >> 5);
    if (n >= NN) return;
    int lane = tid & 31, c0 = lane * 4;

    float4 w0 = *(float4*)&sWe[c0];
    float4 w1 = *(float4*)&sWe[128 + c0];
    float4 at = *(float4*)&sAtt[c0];
    float4 xr = *(const float4*)(g_xr + n * HC + c0);
    float4 xls = *(const float4*)(g_xl + n * HC + c0);

    // self-loop logit (ea = 0)
    float z0 = xls.x + xr.x, z1 = xls.y + xr.y, z2 = xls.z + xr.z, z3 = xls.w + xr.w;
    z0 = z0 > 0.f ? z0 : 0.2f * z0;
    z1 = z1 > 0.f ? z1 : 0.2f * z1;
    z2 = z2 > 0.f ? z2 : 0.2f * z2;
    z3 = z3 > 0.f ? z3 : 0.2f * z3;
    float pself = z0 * at.x + z1 * at.y + z2 * at.z + z3 * at.w;
    pself += __shfl_xor_sync(0xffffffffu, pself, 1);
    pself += __shfl_xor_sync(0xffffffffu, pself, 2);
    pself += __shfl_xor_sync(0xffffffffu, pself, 4);

    int beg = g_rowptr[n], end = g_rowptr[n + 1];

    // online softmax state (per head, replicated across its 8 lanes)
    float m = pself, s = 1.0f;
    float4 acc;
    acc.x = xls.x; acc.y = xls.y; acc.z = xls.z; acc.w = xls.w;

    // software-pipelined edge loop: prefetch next src/ea/xl while computing cur
    int p = beg;
    int src0 = 0; float2 ea0 = make_float2(0.f, 0.f); float4 xl0 = make_float4(0.f, 0.f, 0.f, 0.f);
    if (p < end) {
        src0 = g_csrc[p];
        ea0 = g_cea[p];
        xl0 = *(const float4*)(g_xl + src0 * HC + c0);
    }
    for (; p < end;) {
        float2 eav = ea0;
        float4 xl = xl0;
        int pn = p + 1;
        if (pn < end) {
            int src1 = g_csrc[pn];
            ea0 = g_cea[pn];
            xl0 = *(const float4*)(g_xl + src1 * HC + c0);
        }
        p = pn;

        float y0 = fmaf(eav.x, w0.x, fmaf(eav.y, w1.x, xl.x + xr.x));
        float y1 = fmaf(eav.x, w0.y, fmaf(eav.y, w1.y, xl.y + xr.y));
        float y2 = fmaf(eav.x, w0.z, fmaf(eav.y, w1.z, xl.z + xr.z));
        float y3 = fmaf(eav.x, w0.w, fmaf(eav.y, w1.w, xl.w + xr.w));
        y0 = y0 > 0.f ? y0 : 0.2f * y0;
        y1 = y1 > 0.f ? y1 : 0.2f * y1;
        y2 = y2 > 0.f ? y2 : 0.2f * y2;
        y3 = y3 > 0.f ? y3 : 0.2f * y3;
        float q = y0 * at.x + y1 * at.y + y2 * at.z + y3 * at.w;
        q += __shfl_xor_sync(0xffffffffu, q, 1);
        q += __shfl_xor_sync(0xffffffffu, q, 2);
        q += __shfl_xor_sync(0xffffffffu, q, 4);

        float mn = fmaxf(m, q);
        float eo = __expf(m - mn);     // 1.0 when max unchanged
        float en = __expf(q - mn);
        s = fmaf(s, eo, en);
        acc.x = fmaf(acc.x, eo, en * xl.x);
        acc.y = fmaf(acc.y, eo, en * xl.y);
        acc.z = fmaf(acc.z, eo, en * xl.z);
        acc.w = fmaf(acc.w, eo, en * xl.w);
        m = mn;
    }

    float inv = 1.0f / (s + 1e-16f);
    float4 bv = *(const float4*)(bias + c0);
    float4 o;
    o.x = fmaxf(fmaf(acc.x, inv, bv.x), 0.f);
    o.y = fmaxf(fmaf(acc.y, inv, bv.y), 0.f);
    o.z = fmaxf(fmaf(acc.z, inv, bv.z), 0.f);
    o.w = fmaxf(fmaf(acc.w, inv, bv.w), 0.f);
    if (add_res) {
        float4 r = *(const float4*)(g_res + n * HC + c0);
        o.x += r.x; o.y += r.y; o.z += r.z; o.w += r.w;
    }
    *(float4*)(g_x + n * HC + c0) = o;
    if (write_res) *(float4*)(g_res + n * HC + c0) = o;
}

// ---------------- pooling (exploit sorted batch: local acc, flush on change) ---
__global__ void zero_pool_kernel() {
    int i = blockIdx.x * blockDim.x + threadIdx.x;
    if (i < NB * HC) { g_mean[i] = 0.f; g_maxenc[i] = 0u; }
    if (i < NB) g_cnt[i] = 0.f;
}

#define POOL_CH 200
__global__ void pool_acc_kernel(const int* __restrict__ batch) {
    int c = threadIdx.x;
    int n0 = blockIdx.x * POOL_CH;
    int n1 = n0 + POOL_CH;
    if (n1 > NN) n1 = NN;
    if (n0 >= NN) return;
    int curb = batch[n0];
    float sm = 0.f, mxv = -INFINITY, cnt = 0.f;
    for (int n = n0; n < n1; n++) {
        int b = batch[n];
        if (b != curb) {
            atomicAdd(&g_mean[curb * HC + c], sm);
            atomicMax(&g_maxenc[curb * HC + c], encf(mxv));
            if (c == 0) atomicAdd(&g_cnt[curb], cnt);
            sm = 0.f; mxv = -INFINITY; cnt = 0.f; curb = b;
        }
        float v = g_x[n * HC + c];
        sm += v;
        mxv = fmaxf(mxv, v);
        cnt += 1.f;
    }
    atomicAdd(&g_mean[curb * HC + c], sm);
    atomicMax(&g_maxenc[curb * HC + c], encf(mxv));
    if (c == 0) atomicAdd(&g_cnt[curb], cnt);
}

__global__ void pool_fin_kernel() {
    int i = blockIdx.x * blockDim.x + threadIdx.x;
    if (i >= NB * HC) return;
    int b = i >> 7, c = i & 127;
    float cnt = g_cnt[b];
    g_X[b * 256 + c] = g_mean[i] / fmaxf(cnt, 1.f);
    g_X[b * 256 + 128 + c] = (cnt > 0.f) ? decf(g_maxenc[i]) : 0.f;
}

// ---------------- dense trunk + heads (one block per graph) -------------------
__global__ void dense_kernel(const float* __restrict__ D1W, const float* __restrict__ D1b,
                             const float* __restrict__ D23W, const float* __restrict__ D23b,
                             const float* __restrict__ H1W, const float* __restrict__ H1b,
                             const float* __restrict__ H2W, const float* __restrict__ H2b,
                             const float* __restrict__ H3W, const float* __restrict__ H3b,
                             float* __restrict__ out) {
    __shared__ float sA[256];
    __shared__ float sB[128];
    __shared__ float sX3[128];
    int b = blockIdx.x, t = threadIdx.x;
    sA[t] = g_X[b * 256 + t];
    sA[t + 128] = g_X[b * 256 + 128 + t];
    __syncthreads();
    float acc = D1b[t];
    for (int k = 0; k < 256; k++) acc = fmaf(sA[k], D1W[k * 128 + t], acc);
    acc = fmaxf(acc, 0.f);
    sB[t] = acc;
    __syncthreads();
    acc = D23b[t];
    for (int k = 0; k < 128; k++) acc = fmaf(sB[k], D23W[k * 128 + t], acc);
    acc = fmaxf(acc, 0.f);
    __syncthreads();
    sA[t] = acc;
    __syncthreads();
    acc = D23b[128 + t];
    for (int k = 0; k < 128; k++) acc = fmaf(sA[k], D23W[16384 + k * 128 + t], acc);
    sX3[t] = fmaxf(acc, 0.f);
    __syncthreads();
    for (int h = 0; h < 3; h++) {
        float a1 = H1b[h * 128 + t];
        for (int k = 0; k < 128; k++) a1 = fmaf(sX3[k], H1W[h * 16384 + k * 128 + t], a1);
        a1 = fmaxf(a1, 0.f);
        sB[t] = a1;
        __syncthreads();
        float a2 = 0.f;
        if (t < 64) {
            a2 = H2b[h * 64 + t];
            for (int k = 0; k < 128; k++) a2 = fmaf(sB[k], H2W[h * 8192 + k * 64 + t], a2);
            a2 = fmaxf(a2, 0.f);
        }
        __syncthreads();
        if (t < 64) sA[t] = a2;
        __syncthreads();
        if (t == 0) {
            float y = H3b[h];
            for (int k = 0; k < 64; k++) y = fmaf(sA[k], H3W[h * 64 + k], y);
            if (h == 0) y = tanhf(y);
            out[b * 3 + h] = y;
        }
        __syncthreads();
    }
}

// ---------------- host ---------------------------------------------------------
extern "C" void kernel_launch(void* const* d_in, const int* in_sizes, int n_in,
                              void* d_out, int out_size) {
    const float* nodes = (const float*)d_in[0];
    const int*   ei    = (const int*)d_in[1];
    const float* ea    = (const float*)d_in[2];
    const int*   batch = (const int*)d_in[3];
    const float* W0l = (const float*)d_in[4];
    const float* b0l = (const float*)d_in[5];
    const float* W0r = (const float*)d_in[6];
    const float* b0r = (const float*)d_in[7];
    const float* W0e = (const float*)d_in[8];
    const float* att0 = (const float*)d_in[9];
    const float* bias0 = (const float*)d_in[10];
    const float* Wl = (const float*)d_in[11];
    const float* bl = (const float*)d_in[12];
    const float* Wr = (const float*)d_in[13];
    const float* br = (const float*)d_in[14];
    const float* We = (const float*)d_in[15];
    const float* atts = (const float*)d_in[16];
    const float* biases = (const float*)d_in[17];
    const float* D1W = (const float*)d_in[18];
    const float* D1b = (const float*)d_in[19];
    const float* D23W = (const float*)d_in[20];
    const float* D23b = (const float*)d_in[21];
    const float* H1W = (const float*)d_in[22];
    const float* H1b = (const float*)d_in[23];
    const float* H2W = (const float*)d_in[24];
    const float* H2b = (const float*)d_in[25];
    const float* H3W = (const float*)d_in[26];
    const float* H3b = (const float*)d_in[27];
    float* out = (float*)d_out;

    // CSR build (reused for all 9 layers)
    csr_zero_kernel<<<(NN + 255) / 256, 256>>>();
    csr_hist_kernel<<<(ER + 255) / 256, 256>>>(ei);
    csr_scan_kernel<<<1, 1024>>>();
    csr_scatter_kernel<<<(ER + 255) / 256, 256>>>(ei, ea);

    // conv0 (input dim 4)
    gemm0_kernel<<<(NN * HC + 255) / 256, 256>>>(nodes, W0l, b0l, W0r, b0r);
    gat_layer_kernel<<<(NN + 7) / 8, 256>>>(W0e, att0, bias0, 0, 1);

    // 8 stacked convs (4 skip blocks x 2)
    for (int t = 0; t < 8; t++) {
        gemm_dual_kernel<<<(NN + 63) / 64, 256>>>(Wl + t * 16384, bl + t * 128,
                                                  Wr + t * 16384, br + t * 128);
        int second = (t & 1);
        gat_layer_kernel<<<(NN + 7) / 8, 256>>>(We + t * 256, atts + t * 128,
                                                biases + t * 128, second, second);
    }

    // pooling
    zero_pool_kernel<<<(NB * HC + 255) / 256, 256>>>();
    pool_acc_kernel<<<(NN + POOL_CH - 1) / POOL_CH, 128>>>(batch);
    pool_fin_kernel<<<(NB * HC + 127) / 128, 128>>>();

    // dense trunk + 3 heads
    dense_kernel<<<NB, 128>>>(D1W, D1b, D23W, D23b, H1W, H1b, H2W, H2b, H3W, H3b, out);
}

// round 5
// speedup vs baseline: 3.2873x; 1.6111x over previous
#include <cuda_runtime.h>
#include <cuda_bf16.h>
#include <math.h>
#include <stdint.h>

#define NN 50000
#define ER 600000
#define HC 128
#define NB 50
#define NTILES ((NN + 127) / 128)   // 391

// ---------------- scratch (static device globals; no allocation) -------------
__device__ float    g_x[NN * HC];
__device__ float    g_res[NN * HC];
__device__ float    g_xl[NN * HC];
__device__ float    g_xr[NN * HC];
__device__ int      g_deg[NN];
__device__ int      g_rowptr[NN + 1];
__device__ int      g_cur[NN];
__device__ int      g_csrc[ER];
__device__ float2   g_cea[ER];
__device__ float    g_mean[NB * HC];
__device__ unsigned g_maxenc[NB * HC];
__device__ float    g_cnt[NB];
__device__ float    g_X[NB * 256];
// mma B-fragment images: 8 layers x 2 outputs x 8 ksteps x 16 ntiles x 32 lanes x 4 words
__device__ unsigned g_Bfrag[8 * 2 * 8 * 16 * 32 * 4];   // 262144 words = 1 MB

__device__ __forceinline__ unsigned encf(float f) {
    unsigned u = __float_as_uint(f);
    return (u & 0x80000000u) ? ~u : (u | 0x80000000u);
}
__device__ __forceinline__ float decf(unsigned u) {
    return __uint_as_float((u & 0x80000000u) ? (u & 0x7fffffffu) : ~u);
}
__device__ __forceinline__ unsigned pack_hi2(float x, float y) {
    __nv_bfloat16 hx = __float2bfloat16(x), hy = __float2bfloat16(y);
    return (unsigned)__bfloat16_as_ushort(hx) | ((unsigned)__bfloat16_as_ushort(hy) << 16);
}
__device__ __forceinline__ unsigned pack_lo2(float x, float y) {
    __nv_bfloat16 hx = __float2bfloat16(x), hy = __float2bfloat16(y);
    __nv_bfloat16 lx = __float2bfloat16(x - __bfloat162float(hx));
    __nv_bfloat16 ly = __float2bfloat16(y - __bfloat162float(hy));
    return (unsigned)__bfloat16_as_ushort(lx) | ((unsigned)__bfloat16_as_ushort(ly) << 16);
}

#define MMA16816(d, a0, a1, a2, a3, b0, b1) \
    asm volatile("mma.sync.aligned.m16n8k16.row.col.f32.bf16.bf16.f32 " \
        "{%0,%1,%2,%3}, {%4,%5,%6,%7}, {%8,%9}, {%0,%1,%2,%3};" \
        : "+f"((d)[0]), "+f"((d)[1]), "+f"((d)[2]), "+f"((d)[3]) \
        : "r"(a0), "r"(a1), "r"(a2), "r"(a3), "r"(b0), "r"(b1))

// ---------------- CSR build (once per call) -----------------------------------
__global__ void csr_zero_kernel() {
    int i = blockIdx.x * blockDim.x + threadIdx.x;
    if (i < NN) g_deg[i] = 0;
}
__global__ void csr_hist_kernel(const int* __restrict__ ei) {
    int e = blockIdx.x * blockDim.x + threadIdx.x;
    if (e < ER) atomicAdd(&g_deg[ei[ER + e]], 1);
}
__global__ void csr_scan_kernel() {
    __shared__ int ps[1024];
    int t = threadIdx.x;
    const int CH = (NN + 1023) / 1024;
    int base = t * CH;
    int sum = 0;
    for (int j = 0; j < CH; j++) {
        int i = base + j;
        if (i < NN) sum += g_deg[i];
    }
    ps[t] = sum;
    __syncthreads();
    for (int off = 1; off < 1024; off <<= 1) {
        int v = (t >= off) ? ps[t - off] : 0;
        __syncthreads();
        ps[t] += v;
        __syncthreads();
    }
    int run = (t == 0) ? 0 : ps[t - 1];
    for (int j = 0; j < CH; j++) {
        int i = base + j;
        if (i < NN) {
            g_rowptr[i] = run;
            g_cur[i] = run;
            run += g_deg[i];
        }
    }
    if (t == 1023) g_rowptr[NN] = ps[1023];
}
__global__ void csr_scatter_kernel(const int* __restrict__ ei, const float* __restrict__ ea) {
    int e = blockIdx.x * blockDim.x + threadIdx.x;
    if (e >= ER) return;
    int s = ei[e], d = ei[ER + e];
    int p = atomicAdd(&g_cur[d], 1);
    g_csrc[p] = s;
    g_cea[p] = make_float2(ea[2 * e], ea[2 * e + 1]);
}

// ---------------- weight prepass: W -> per-lane mma B fragments ----------------
// word index i = ((((layer*2+o)*8 + kstep)*16 + nt)*32 + lane)*4 + reg
// reg 0 = bhi(k0..k0+1), 1 = bhi(k0+8..), 2 = blo(k0..), 3 = blo(k0+8..)
__global__ void wprep_kernel(const float* __restrict__ Wl, const float* __restrict__ Wr) {
    int i = blockIdx.x * blockDim.x + threadIdx.x;
    if (i >= 262144) return;
    int reg = i & 3;
    int lane = (i >> 2) & 31;
    int nt = (i >> 7) & 15;
    int kstep = (i >> 11) & 7;
    int o = (i >> 14) & 1;
    int t = i >> 15;
    const float* W = (o ? Wr : Wl) + t * 16384;
    int n = nt * 8 + (lane >> 2);
    int k = kstep * 16 + (lane & 3) * 2 + ((reg & 1) ? 8 : 0);
    float v0 = W[k * 128 + n];
    float v1 = W[(k + 1) * 128 + n];
    g_Bfrag[i] = (reg < 2) ? pack_hi2(v0, v1) : pack_lo2(v0, v1);
}

// ---------------- conv0 linear (K=4) -----------------------------------------
__global__ void gemm0_kernel(const float* __restrict__ nodes,
                             const float* __restrict__ W0l, const float* __restrict__ b0l,
                             const float* __restrict__ W0r, const float* __restrict__ b0r) {
    int i = blockIdx.x * blockDim.x + threadIdx.x;
    if (i >= NN * HC) return;
    int n = i >> 7, c = i & 127;
    float4 nd = *(const float4*)(nodes + n * 4);
    float l = b0l[c] + nd.x * W0l[c] + nd.y * W0l[128 + c] + nd.z * W0l[256 + c] + nd.w * W0l[384 + c];
    float r = b0r[c] + nd.x * W0r[c] + nd.y * W0r[128 + c] + nd.z * W0r[256 + c] + nd.w * W0r[384 + c];
    g_xl[i] = l;
    g_xr[i] = r;
}

// ---------------- mma.sync dual GEMM: xl = x@Wl+bl, xr = x@Wr+br ---------------
// block 256 thr = 8 warps x 16 rows = 128-row tile; bf16 hi/lo, fp32 accum.
// smem: Ahi[128][68] words, Alo[128][68] words, Bfrag 16384 words
#define GSM_ALO 34816
#define GSM_B   69632
#define GSM_TOTAL (69632 + 65536)   // 135168 B

__global__ void __launch_bounds__(256) gemm_mma_kernel(
        int layer, const float* __restrict__ bl, const float* __restrict__ br) {
    extern __shared__ __align__(16) char smem[];
    unsigned* Ahi = (unsigned*)smem;
    unsigned* Alo = (unsigned*)(smem + GSM_ALO);
    uint4*    Bs  = (uint4*)(smem + GSM_B);
    int tid = threadIdx.x, wid = tid >> 5, lane = tid & 31;
    int row0 = blockIdx.x * 128;

    // stage A as bf16 hi/lo (padded 68 words/row -> conflict-free frag reads)
    for (int j = tid; j < 4096; j += 256) {   // 128 rows x 32 float4
        int r = j >> 5, c4 = j & 31;
        int gr = row0 + r;
        float4 v = (gr < NN) ? *(const float4*)(g_x + gr * HC + c4 * 4)
                             : make_float4(0.f, 0.f, 0.f, 0.f);
        int w = r * 68 + c4 * 2;
        Ahi[w]     = pack_hi2(v.x, v.y);
        Ahi[w + 1] = pack_hi2(v.z, v.w);
        Alo[w]     = pack_lo2(v.x, v.y);
        Alo[w + 1] = pack_lo2(v.z, v.w);
    }

    for (int o = 0; o < 2; o++) {
        const uint4* src = (const uint4*)g_Bfrag + (layer * 2 + o) * 4096;
        for (int j = tid; j < 4096; j += 256) Bs[j] = src[j];
        __syncthreads();

        float d[16][4];
#pragma unroll
        for (int nt = 0; nt < 16; nt++) {
            d[nt][0] = 0.f; d[nt][1] = 0.f; d[nt][2] = 0.f; d[nt][3] = 0.f;
        }
        int ab = (wid * 16 + (lane >> 2)) * 68 + (lane & 3);
#pragma unroll
        for (int ks = 0; ks < 8; ks++) {
            unsigned ah0 = Ahi[ab + ks * 8];
            unsigned ah1 = Ahi[ab + 8 * 68 + ks * 8];
            unsigned ah2 = Ahi[ab + ks * 8 + 4];
            unsigned ah3 = Ahi[ab + 8 * 68 + ks * 8 + 4];
            unsigned al0 = Alo[ab + ks * 8];
            unsigned al1 = Alo[ab + 8 * 68 + ks * 8];
            unsigned al2 = Alo[ab + ks * 8 + 4];
            unsigned al3 = Alo[ab + 8 * 68 + ks * 8 + 4];
#pragma unroll
            for (int nt = 0; nt < 16; nt++) {
                uint4 b = Bs[(ks * 16 + nt) * 32 + lane];
                MMA16816(d[nt], ah0, ah1, ah2, ah3, b.x, b.y);   // hi·hi
                MMA16816(d[nt], ah0, ah1, ah2, ah3, b.z, b.w);   // hi·lo
                MMA16816(d[nt], al0, al1, al2, al3, b.x, b.y);   // lo·hi
            }
        }
        __syncthreads();   // all warps done with Bs before next overwrite

        const float* bias = o ? br : bl;
        float* dst = o ? g_xr : g_xl;
        int r = row0 + wid * 16 + (lane >> 2);
        int cb = (lane & 3) * 2;
#pragma unroll
        for (int nt = 0; nt < 16; nt++) {
            int c = nt * 8 + cb;
            if (r < NN) {
                float2 v = make_float2(d[nt][0] + bias[c], d[nt][1] + bias[c + 1]);
                *(float2*)(dst + r * HC + c) = v;
            }
            if (r + 8 < NN) {
                float2 v = make_float2(d[nt][2] + bias[c], d[nt][3] + bias[c + 1]);
                *(float2*)(dst + (r + 8) * HC + c) = v;
            }
        }
    }
}

// ---------------- fused GATv2 layer: warp per dst node, single-pass softmax ---
__global__ void __launch_bounds__(256) gat_layer_kernel(
        const float* __restrict__ We, const float* __restrict__ att,
        const float* __restrict__ bias, int add_res, int write_res) {
    __shared__ float sWe[256];
    __shared__ float sAtt[128];
    int tid = threadIdx.x;
    if (tid < 256) sWe[tid] = We[tid];
    if (tid < 128) sAtt[tid] = att[tid];
    __syncthreads();

    int n = blockIdx.x * 8 + (tid >> 5);
    if (n >= NN) return;
    int lane = tid & 31, c0 = lane * 4;

    float4 w0 = *(float4*)&sWe[c0];
    float4 w1 = *(float4*)&sWe[128 + c0];
    float4 at = *(float4*)&sAtt[c0];
    float4 xr = *(const float4*)(g_xr + n * HC + c0);
    float4 xls = *(const float4*)(g_xl + n * HC + c0);

    // self-loop logit (ea = 0)
    float z0 = xls.x + xr.x, z1 = xls.y + xr.y, z2 = xls.z + xr.z, z3 = xls.w + xr.w;
    z0 = z0 > 0.f ? z0 : 0.2f * z0;
    z1 = z1 > 0.f ? z1 : 0.2f * z1;
    z2 = z2 > 0.f ? z2 : 0.2f * z2;
    z3 = z3 > 0.f ? z3 : 0.2f * z3;
    float pself = z0 * at.x + z1 * at.y + z2 * at.z + z3 * at.w;
    pself += __shfl_xor_sync(0xffffffffu, pself, 1);
    pself += __shfl_xor_sync(0xffffffffu, pself, 2);
    pself += __shfl_xor_sync(0xffffffffu, pself, 4);

    int beg = g_rowptr[n], end = g_rowptr[n + 1];

    float m = pself, s = 1.0f;
    float4 acc;
    acc.x = xls.x; acc.y = xls.y; acc.z = xls.z; acc.w = xls.w;

    // 2-deep software pipeline over incoming edges
    float2 eaA = make_float2(0.f, 0.f), eaB = eaA;
    float4 xlA = make_float4(0.f, 0.f, 0.f, 0.f), xlB = xlA;
    if (beg < end) {
        int s0 = g_csrc[beg];
        eaA = g_cea[beg];
        xlA = *(const float4*)(g_xl + s0 * HC + c0);
    }
    if (beg + 1 < end) {
        int s1 = g_csrc[beg + 1];
        eaB = g_cea[beg + 1];
        xlB = *(const float4*)(g_xl + s1 * HC + c0);
    }
    for (int p = beg; p < end; p++) {
        float2 eav = eaA;
        float4 xl = xlA;
        eaA = eaB; xlA = xlB;
        int pf = p + 2;
        if (pf < end) {
            int sf = g_csrc[pf];
            eaB = g_cea[pf];
            xlB = *(const float4*)(g_xl + sf * HC + c0);
        }

        float y0 = fmaf(eav.x, w0.x, fmaf(eav.y, w1.x, xl.x + xr.x));
        float y1 = fmaf(eav.x, w0.y, fmaf(eav.y, w1.y, xl.y + xr.y));
        float y2 = fmaf(eav.x, w0.z, fmaf(eav.y, w1.z, xl.z + xr.z));
        float y3 = fmaf(eav.x, w0.w, fmaf(eav.y, w1.w, xl.w + xr.w));
        y0 = y0 > 0.f ? y0 : 0.2f * y0;
        y1 = y1 > 0.f ? y1 : 0.2f * y1;
        y2 = y2 > 0.f ? y2 : 0.2f * y2;
        y3 = y3 > 0.f ? y3 : 0.2f * y3;
        float q = y0 * at.x + y1 * at.y + y2 * at.z + y3 * at.w;
        q += __shfl_xor_sync(0xffffffffu, q, 1);
        q += __shfl_xor_sync(0xffffffffu, q, 2);
        q += __shfl_xor_sync(0xffffffffu, q, 4);

        float diff = q - m;
        float ex = __expf(-fabsf(diff));
        bool up = diff > 0.f;
        float en = up ? 1.f : ex;
        float eo = up ? ex : 1.f;
        s = fmaf(s, eo, en);
        acc.x = fmaf(acc.x, eo, en * xl.x);
        acc.y = fmaf(acc.y, eo, en * xl.y);
        acc.z = fmaf(acc.z, eo, en * xl.z);
        acc.w = fmaf(acc.w, eo, en * xl.w);
        m = up ? q : m;
    }

    float inv = 1.0f / (s + 1e-16f);
    float4 bv = *(const float4*)(bias + c0);
    float4 o;
    o.x = fmaxf(fmaf(acc.x, inv, bv.x), 0.f);
    o.y = fmaxf(fmaf(acc.y, inv, bv.y), 0.f);
    o.z = fmaxf(fmaf(acc.z, inv, bv.z), 0.f);
    o.w = fmaxf(fmaf(acc.w, inv, bv.w), 0.f);
    if (add_res) {
        float4 r = *(const float4*)(g_res + n * HC + c0);
        o.x += r.x; o.y += r.y; o.z += r.z; o.w += r.w;
    }
    *(float4*)(g_x + n * HC + c0) = o;
    if (write_res) *(float4*)(g_res + n * HC + c0) = o;
}

// ---------------- pooling ------------------------------------------------------
__global__ void zero_pool_kernel() {
    int i = blockIdx.x * blockDim.x + threadIdx.x;
    if (i < NB * HC) { g_mean[i] = 0.f; g_maxenc[i] = 0u; }
    if (i < NB) g_cnt[i] = 0.f;
}

#define POOL_CH 200
__global__ void pool_acc_kernel(const int* __restrict__ batch) {
    int c = threadIdx.x;
    int n0 = blockIdx.x * POOL_CH;
    int n1 = n0 + POOL_CH;
    if (n1 > NN) n1 = NN;
    if (n0 >= NN) return;
    int curb = batch[n0];
    float sm = 0.f, mxv = -INFINITY, cnt = 0.f;
    for (int n = n0; n < n1; n++) {
        int b = batch[n];
        if (b != curb) {
            atomicAdd(&g_mean[curb * HC + c], sm);
            atomicMax(&g_maxenc[curb * HC + c], encf(mxv));
            if (c == 0) atomicAdd(&g_cnt[curb], cnt);
            sm = 0.f; mxv = -INFINITY; cnt = 0.f; curb = b;
        }
        float v = g_x[n * HC + c];
        sm += v;
        mxv = fmaxf(mxv, v);
        cnt += 1.f;
    }
    atomicAdd(&g_mean[curb * HC + c], sm);
    atomicMax(&g_maxenc[curb * HC + c], encf(mxv));
    if (c == 0) atomicAdd(&g_cnt[curb], cnt);
}

__global__ void pool_fin_kernel() {
    int i = blockIdx.x * blockDim.x + threadIdx.x;
    if (i >= NB * HC) return;
    int b = i >> 7, c = i & 127;
    float cnt = g_cnt[b];
    g_X[b * 256 + c] = g_mean[i] / fmaxf(cnt, 1.f);
    g_X[b * 256 + 128 + c] = (cnt > 0.f) ? decf(g_maxenc[i]) : 0.f;
}

// ---------------- dense trunk + heads (one block per graph) -------------------
__global__ void dense_kernel(const float* __restrict__ D1W, const float* __restrict__ D1b,
                             const float* __restrict__ D23W, const float* __restrict__ D23b,
                             const float* __restrict__ H1W, const float* __restrict__ H1b,
                             const float* __restrict__ H2W, const float* __restrict__ H2b,
                             const float* __restrict__ H3W, const float* __restrict__ H3b,
                             float* __restrict__ out) {
    __shared__ float sA[256];
    __shared__ float sB[128];
    __shared__ float sX3[128];
    int b = blockIdx.x, t = threadIdx.x;
    sA[t] = g_X[b * 256 + t];
    sA[t + 128] = g_X[b * 256 + 128 + t];
    __syncthreads();
    float acc = D1b[t];
    for (int k = 0; k < 256; k++) acc = fmaf(sA[k], D1W[k * 128 + t], acc);
    acc = fmaxf(acc, 0.f);
    sB[t] = acc;
    __syncthreads();
    acc = D23b[t];
    for (int k = 0; k < 128; k++) acc = fmaf(sB[k], D23W[k * 128 + t], acc);
    acc = fmaxf(acc, 0.f);
    __syncthreads();
    sA[t] = acc;
    __syncthreads();
    acc = D23b[128 + t];
    for (int k = 0; k < 128; k++) acc = fmaf(sA[k], D23W[16384 + k * 128 + t], acc);
    sX3[t] = fmaxf(acc, 0.f);
    __syncthreads();
    for (int h = 0; h < 3; h++) {
        float a1 = H1b[h * 128 + t];
        for (int k = 0; k < 128; k++) a1 = fmaf(sX3[k], H1W[h * 16384 + k * 128 + t], a1);
        a1 = fmaxf(a1, 0.f);
        sB[t] = a1;
        __syncthreads();
        float a2 = 0.f;
        if (t < 64) {
            a2 = H2b[h * 64 + t];
            for (int k = 0; k < 128; k++) a2 = fmaf(sB[k], H2W[h * 8192 + k * 64 + t], a2);
            a2 = fmaxf(a2, 0.f);
        }
        __syncthreads();
        if (t < 64) sA[t] = a2;
        __syncthreads();
        if (t == 0) {
            float y = H3b[h];
            for (int k = 0; k < 64; k++) y = fmaf(sA[k], H3W[h * 64 + k], y);
            if (h == 0) y = tanhf(y);
            out[b * 3 + h] = y;
        }
        __syncthreads();
    }
}

// ---------------- host ---------------------------------------------------------
extern "C" void kernel_launch(void* const* d_in, const int* in_sizes, int n_in,
                              void* d_out, int out_size) {
    const float* nodes = (const float*)d_in[0];
    const int*   ei    = (const int*)d_in[1];
    const float* ea    = (const float*)d_in[2];
    const int*   batch = (const int*)d_in[3];
    const float* W0l = (const float*)d_in[4];
    const float* b0l = (const float*)d_in[5];
    const float* W0r = (const float*)d_in[6];
    const float* b0r = (const float*)d_in[7];
    const float* W0e = (const float*)d_in[8];
    const float* att0 = (const float*)d_in[9];
    const float* bias0 = (const float*)d_in[10];
    const float* Wl = (const float*)d_in[11];
    const float* bl = (const float*)d_in[12];
    const float* Wr = (const float*)d_in[13];
    const float* br = (const float*)d_in[14];
    const float* We = (const float*)d_in[15];
    const float* atts = (const float*)d_in[16];
    const float* biases = (const float*)d_in[17];
    const float* D1W = (const float*)d_in[18];
    const float* D1b = (const float*)d_in[19];
    const float* D23W = (const float*)d_in[20];
    const float* D23b = (const float*)d_in[21];
    const float* H1W = (const float*)d_in[22];
    const float* H1b = (const float*)d_in[23];
    const float* H2W = (const float*)d_in[24];
    const float* H2b = (const float*)d_in[25];
    const float* H3W = (const float*)d_in[26];
    const float* H3b = (const float*)d_in[27];
    float* out = (float*)d_out;

    cudaFuncSetAttribute(gemm_mma_kernel,
                         cudaFuncAttributeMaxDynamicSharedMemorySize, GSM_TOTAL);

    // CSR build + weight fragment prepass (reused for all layers)
    csr_zero_kernel<<<(NN + 255) / 256, 256>>>();
    csr_hist_kernel<<<(ER + 255) / 256, 256>>>(ei);
    csr_scan_kernel<<<1, 1024>>>();
    csr_scatter_kernel<<<(ER + 255) / 256, 256>>>(ei, ea);
    wprep_kernel<<<1024, 256>>>(Wl, Wr);

    // conv0 (input dim 4)
    gemm0_kernel<<<(NN * HC + 255) / 256, 256>>>(nodes, W0l, b0l, W0r, b0r);
    gat_layer_kernel<<<(NN + 7) / 8, 256>>>(W0e, att0, bias0, 0, 1);

    // 8 stacked convs (4 skip blocks x 2)
    for (int t = 0; t < 8; t++) {
        gemm_mma_kernel<<<NTILES, 256, GSM_TOTAL>>>(t, bl + t * 128, br + t * 128);
        int second = (t & 1);
        gat_layer_kernel<<<(NN + 7) / 8, 256>>>(We + t * 256, atts + t * 128,
                                                biases + t * 128, second, second);
    }

    // pooling
    zero_pool_kernel<<<(NB * HC + 255) / 256, 256>>>();
    pool_acc_kernel<<<(NN + POOL_CH - 1) / POOL_CH, 128>>>(batch);
    pool_fin_kernel<<<(NB * HC + 127) / 128, 128>>>();

    // dense trunk + 3 heads
    dense_kernel<<<NB, 128>>>(D1W, D1b, D23W, D23b, H1W, H1b, H2W, H2b, H3W, H3b, out);
}